// round 16
// baseline (speedup 1.0000x reference)
#include <cuda_runtime.h>
#include <cuda_fp16.h>
#include <math.h>

#define NSP   16384
#define NPIX  (512*512)
#define NE    262144
#define CAP   64        // max entries per segment (mean 16, 12-sigma bound)

// ---------------------------------------------------------------------------
// Static scratch (no allocations allowed)
// ---------------------------------------------------------------------------
struct __align__(256) Scratch {
    __half sp [NSP * 128];    // pooled superpixel features (fp16)
    __half hb0[NSP * 128];    // layer ping (fp16)
    __half hb1[NSP * 128];    // layer pong (fp16)
    __half h4h[NSP * 128];    // H1+H2+H3 (fp16, A input of P-GEMM)
    float  h4 [NSP * 128];    // H1+H2+H3 fp32 accumulator
    float  abA[NSP * 128];    // per-node A-half (fp32)
    __half abB[NSP * 128];    // per-node B-half (fp16, gathered by segmax)
    __half wp1t[256 * 128];   // W1 folded, TRANSPOSED [n][k] fp16
    __half wp2t[256 * 128];   // W2 folded, TRANSPOSED [n][k] fp16
    __half wfoldt[144 * 128]; // folded conv*linear, TRANSPOSED [n][k] fp16
    float  biasf[16];         // bc@Wl + bl (full precision)
    __half Ph[NSP * 144];     // per-superpixel tap contributions (fp16)
    int cnt_pix[NSP];
    int cnt_e  [NSP];
    int pix_lst[NSP * CAP];
    int src_lst[NSP * CAP];
};
__device__ Scratch g_s;

// ---------------------------------------------------------------------------
// Small helpers
// ---------------------------------------------------------------------------
__device__ __forceinline__ float4 f4max(float4 a, float4 b) {
    return make_float4(fmaxf(a.x, b.x), fmaxf(a.y, b.y),
                       fmaxf(a.z, b.z), fmaxf(a.w, b.w));
}
__device__ __forceinline__ float4 f4add(float4 a, float4 b) {
    return make_float4(a.x + b.x, a.y + b.y, a.z + b.z, a.w + b.w);
}
__device__ __forceinline__ float4 h4tof4(uint2 u) {
    __half2 h0 = *reinterpret_cast<__half2*>(&u.x);
    __half2 h1 = *reinterpret_cast<__half2*>(&u.y);
    float2 f0 = __half22float2(h0), f1 = __half22float2(h1);
    return make_float4(f0.x, f0.y, f1.x, f1.y);
}
__device__ __forceinline__ uint2 f4toh4(float4 v) {
    __half2 p0 = __floats2half2_rn(v.x, v.y);
    __half2 p1 = __floats2half2_rn(v.z, v.w);
    uint2 u;
    u.x = *reinterpret_cast<unsigned*>(&p0);
    u.y = *reinterpret_cast<unsigned*>(&p1);
    return u;
}

// ---------------------------------------------------------------------------
// Fused prep: zero counters + transposed fp16 weights + biasf
// ---------------------------------------------------------------------------
__global__ void k_prep(int* __restrict__ cnts,
                       const float* __restrict__ W1, __half* __restrict__ Wp1t,
                       const float* __restrict__ W2, __half* __restrict__ Wp2t,
                       const float* __restrict__ Wc, const float* __restrict__ Wl,
                       const float* __restrict__ bc, const float* __restrict__ bl,
                       __half* __restrict__ wfoldt, float* __restrict__ biasf) {
    int t = blockIdx.x * blockDim.x + threadIdx.x;
    if (t < 2 * NSP) {
        cnts[t] = 0;
    } else if (t < 2 * NSP + 2 * 32768) {
        int u = t - 2 * NSP;
        const float* W = (u < 32768) ? W1 : W2;
        __half* Wp = (u < 32768) ? Wp1t : Wp2t;
        u &= 32767;
        int n = u >> 7, k = u & 127;      // [n][k] layout
        float v;
        if (n < 128) v = W[k * 128 + n] - W[(k + 128) * 128 + n];
        else         v = W[(k + 128) * 128 + (n - 128)];
        Wp[u] = __float2half_rn(v);
    } else if (t < 2 * NSP + 2 * 32768 + 144 * 128) {
        int u = t - (2 * NSP + 2 * 32768);
        int o = u & 127;                  // k index
        int ntap = u >> 7;                // 0..143: tap*16 + n
        int tap = ntap >> 4, n = ntap & 15;
        float sm = 0.f;
        for (int c = 0; c < 128; c++)
            sm += Wc[(size_t)(c * 128 + o) * 9 + tap] * Wl[c * 16 + n];
        wfoldt[u] = __float2half_rn(sm);
    } else if (t < 2 * NSP + 2 * 32768 + 144 * 128 + 16) {
        int n = t - (2 * NSP + 2 * 32768 + 144 * 128);
        float sm = bl[n];
        for (int c = 0; c < 128; c++) sm += bc[c] * Wl[c * 16 + n];
        biasf[n] = sm;
    }
}

// ---------------------------------------------------------------------------
// Direct scatter into padded CSR (counter = degree). One pass, no scan.
// ---------------------------------------------------------------------------
__global__ void k_scat_both(const int* __restrict__ seg, int* __restrict__ cpix,
                            int* __restrict__ plst, const int* __restrict__ ei,
                            int* __restrict__ ce, int* __restrict__ elst) {
    int i = blockIdx.x * blockDim.x + threadIdx.x;
    {
        int k = seg[i];
        int p = atomicAdd(&cpix[k], 1);
        if (p < CAP) plst[k * CAP + p] = i;
    }
    {
        int d = ei[NE + i];
        int p = atomicAdd(&ce[d], 1);
        if (p < CAP) elst[d * CAP + p] = ei[i];
    }
}

// ---------------------------------------------------------------------------
// Mean pooling: one warp per superpixel; fp16 output (GEMM A input)
// ---------------------------------------------------------------------------
__global__ void k_pool(const float* __restrict__ x, const int* __restrict__ cnt,
                       const int* __restrict__ lst, __half* __restrict__ sp) {
    int w = (blockIdx.x * blockDim.x + threadIdx.x) >> 5;
    if (w >= NSP) return;
    int lane = threadIdx.x & 31;
    int c = cnt[w];
    int n = c < CAP ? c : CAP;
    int base = w * CAP;
    float4 acc = make_float4(0.f, 0.f, 0.f, 0.f);
    int j = 0;
    for (; j + 4 <= n; j += 4) {
        int p0 = lst[base + j], p1 = lst[base + j + 1];
        int p2 = lst[base + j + 2], p3 = lst[base + j + 3];
        float4 v0 = ((const float4*)(x + (size_t)p0 * 128))[lane];
        float4 v1 = ((const float4*)(x + (size_t)p1 * 128))[lane];
        float4 v2 = ((const float4*)(x + (size_t)p2 * 128))[lane];
        float4 v3 = ((const float4*)(x + (size_t)p3 * 128))[lane];
        acc = f4add(acc, f4add(f4add(v0, v1), f4add(v2, v3)));
    }
    for (; j < n; j++) {
        int p = lst[base + j];
        acc = f4add(acc, ((const float4*)(x + (size_t)p * 128))[lane]);
    }
    float inv = 1.0f / fmaxf((float)c, 1.0f);
    acc.x *= inv; acc.y *= inv; acc.z *= inv; acc.w *= inv;
    ((uint2*)(sp + (size_t)w * 128))[lane] = f4toh4(acc);
}

// ---------------------------------------------------------------------------
// FP16 tensor-core GEMM, cp.async 2-stage, 8 warps (4x2), BM=128 BN=64 BK=32.
// A [M][128] fp16 row-major; Bt [N][128] fp16 (transposed: n-major).
// Smem rows stored as u32 with stride 20 (16 payload + 4 pad): conflict-free.
// mode 1: split -> CmA fp32 (stride 128) / CmB fp16 (stride 128). N=256.
// mode 2: fp16 C[M,N] into CmB (row stride N), col-guarded.
// ---------------------------------------------------------------------------
#define CPA(dst, src, sz) \
    asm volatile("cp.async.cg.shared.global [%0], [%1], 16, %2;" \
                 :: "r"(dst), "l"(src), "r"(sz))

__global__ void k_gemm_tc(const __half* __restrict__ A, const __half* __restrict__ Bt,
                          float* __restrict__ Cm, __half* __restrict__ CmB,
                          int M, int N, int mode) {
    __shared__ unsigned smw[2 * 128 * 20 + 2 * 64 * 20];   // 30 KB
    int tid = threadIdx.x;
    int warp = tid >> 5, lane = tid & 31;
    int g = lane >> 2, t = lane & 3;
    int wm = warp & 3, wn = warp >> 2;
    int row0 = blockIdx.y * 128, col0 = blockIdx.x * 64;

    int arow = tid >> 2, aq = tid & 3;
    int brow = tid >> 2, bq = tid & 3;
    int bn = col0 + brow;
    int bsz = (bn < N) ? 16 : 0;
    int bnc = (bn < N) ? bn : 0;
    const __half* aSrc = A + (size_t)(row0 + arow) * 128 + aq * 8;
    const __half* bSrc = Bt + (size_t)bnc * 128 + bq * 8;

    unsigned sbase = (unsigned)__cvta_generic_to_shared(smw);
    unsigned aDst0 = sbase + (unsigned)(arow * 20 + aq * 4) * 4;
    unsigned bDst0 = sbase + (unsigned)(2 * 128 * 20 + brow * 20 + bq * 4) * 4;

#pragma unroll
    for (int it = 0; it < 2; it++)
        CPA(aDst0 + it * (64 * 20 * 4), aSrc + (size_t)(it * 64) * 128, 16);
    CPA(bDst0, bSrc, bsz);
    asm volatile("cp.async.commit_group;");

    float c[2][4][4] = {};
#pragma unroll
    for (int k0i = 0; k0i < 4; k0i++) {
        if (k0i < 3) {
            int s1 = (k0i + 1) & 1;
            int k1 = (k0i + 1) * 32;
            unsigned aD = aDst0 + s1 * (128 * 20 * 4);
            unsigned bD = bDst0 + s1 * (64 * 20 * 4);
#pragma unroll
            for (int it = 0; it < 2; it++)
                CPA(aD + it * (64 * 20 * 4), aSrc + (size_t)(it * 64) * 128 + k1, 16);
            CPA(bD, bSrc + k1, bsz);
            asm volatile("cp.async.commit_group;");
            asm volatile("cp.async.wait_group 1;");
        } else {
            asm volatile("cp.async.wait_group 0;");
        }
        __syncthreads();

        const unsigned* As = smw + (k0i & 1) * (128 * 20);
        const unsigned* Bs = smw + 2 * 128 * 20 + (k0i & 1) * (64 * 20);
#pragma unroll
        for (int ks = 0; ks < 2; ks++) {          // K=16 per step
            int k8 = ks * 8;
            unsigned a[2][4], b[4][2];
#pragma unroll
            for (int i = 0; i < 2; i++) {
                int rm = wm * 32 + i * 16;
                a[i][0] = As[(rm + g) * 20 + k8 + t];
                a[i][1] = As[(rm + g + 8) * 20 + k8 + t];
                a[i][2] = As[(rm + g) * 20 + k8 + 4 + t];
                a[i][3] = As[(rm + g + 8) * 20 + k8 + 4 + t];
            }
#pragma unroll
            for (int j = 0; j < 4; j++) {
                int cn = wn * 32 + j * 8 + g;
                b[j][0] = Bs[cn * 20 + k8 + t];
                b[j][1] = Bs[cn * 20 + k8 + 4 + t];
            }
#pragma unroll
            for (int i = 0; i < 2; i++)
#pragma unroll
                for (int j = 0; j < 4; j++) {
                    asm volatile(
                        "mma.sync.aligned.m16n8k16.row.col.f32.f16.f16.f32 "
                        "{%0,%1,%2,%3}, {%4,%5,%6,%7}, {%8,%9}, {%0,%1,%2,%3};"
                        : "+f"(c[i][j][0]), "+f"(c[i][j][1]),
                          "+f"(c[i][j][2]), "+f"(c[i][j][3])
                        : "r"(a[i][0]), "r"(a[i][1]), "r"(a[i][2]), "r"(a[i][3]),
                          "r"(b[j][0]), "r"(b[j][1]));
                }
        }
        __syncthreads();
    }
    if (mode == 2) {
        // fp16 C, row stride N, col-guarded
#pragma unroll
        for (int i = 0; i < 2; i++) {
            int r = row0 + wm * 32 + i * 16 + g;
#pragma unroll
            for (int j = 0; j < 4; j++) {
                int cc = col0 + wn * 32 + j * 8 + 2 * t;
                if (cc < N) {
                    *(__half2*)(CmB + (size_t)r * N + cc) =
                        __floats2half2_rn(c[i][j][0], c[i][j][1]);
                    *(__half2*)(CmB + (size_t)(r + 8) * N + cc) =
                        __floats2half2_rn(c[i][j][2], c[i][j][3]);
                }
            }
        }
    } else if (col0 < 128) {
#pragma unroll
        for (int i = 0; i < 2; i++) {
            int r = row0 + wm * 32 + i * 16 + g;
#pragma unroll
            for (int j = 0; j < 4; j++) {
                int cc = col0 + wn * 32 + j * 8 + 2 * t;
                *(float2*)(Cm + (size_t)r * 128 + cc) = make_float2(c[i][j][0], c[i][j][1]);
                *(float2*)(Cm + (size_t)(r + 8) * 128 + cc) = make_float2(c[i][j][2], c[i][j][3]);
            }
        }
    } else {
#pragma unroll
        for (int i = 0; i < 2; i++) {
            int r = row0 + wm * 32 + i * 16 + g;
#pragma unroll
            for (int j = 0; j < 4; j++) {
                int cc2 = (col0 - 128) + wn * 32 + j * 8 + 2 * t;
                *(__half2*)(CmB + (size_t)r * 128 + cc2) =
                    __floats2half2_rn(c[i][j][0], c[i][j][1]);
                *(__half2*)(CmB + (size_t)(r + 8) * 128 + cc2) =
                    __floats2half2_rn(c[i][j][2], c[i][j][3]);
            }
        }
    }
}

// ---------------------------------------------------------------------------
// Segmented max + relu, fp16 B gather, high MLP. hout written fp16.
// accum: 0 = h4 init, 1 = h4 +=, 2 = h4h = fp16(h4 + o) [final].
// ---------------------------------------------------------------------------
__global__ void k_segmax(const float* __restrict__ Aarr, const __half* __restrict__ Barr,
                         const float* __restrict__ bias,
                         const int* __restrict__ cnt, const int* __restrict__ lst,
                         __half* __restrict__ hout, float* __restrict__ h4,
                         __half* __restrict__ h4h, int accum) {
    int w = (blockIdx.x * blockDim.x + threadIdx.x) >> 5;
    if (w >= NSP) return;
    int lane = threadIdx.x & 31;
    int c = cnt[w];
    int n = c < CAP ? c : CAP;
    int base = w * CAP;
    int idxA = (lane < n)      ? lst[base + lane]      : 0;
    int idxB = (32 + lane < n) ? lst[base + 32 + lane] : 0;

    float4 mv = make_float4(-INFINITY, -INFINITY, -INFINITY, -INFINITY);
    int j = 0;
    for (; j + 8 <= n; j += 8) {
        uint2 v[8];
#pragma unroll
        for (int u = 0; u < 8; u++) {
            int jj = j + u;
            int s0 = __shfl_sync(~0u, jj < 32 ? idxA : idxB, jj & 31);
            v[u] = ((const uint2*)(Barr + (size_t)s0 * 128))[lane];
        }
#pragma unroll
        for (int u = 0; u < 8; u++) mv = f4max(mv, h4tof4(v[u]));
    }
    for (; j < n; j++) {
        int s0 = __shfl_sync(~0u, j < 32 ? idxA : idxB, j & 31);
        mv = f4max(mv, h4tof4(((const uint2*)(Barr + (size_t)s0 * 128))[lane]));
    }
    float4 a  = ((const float4*)(Aarr + (size_t)w * 128))[lane];
    float4 bb = ((const float4*)bias)[lane];
    float4 o = make_float4(fmaxf(0.f, a.x + bb.x + mv.x),
                           fmaxf(0.f, a.y + bb.y + mv.y),
                           fmaxf(0.f, a.z + bb.z + mv.z),
                           fmaxf(0.f, a.w + bb.w + mv.w));
    ((uint2*)(hout + (size_t)w * 128))[lane] = f4toh4(o);
    float4* hp = (float4*)(h4 + (size_t)w * 128);
    if (accum == 0)      hp[lane] = o;
    else if (accum == 1) { float4 tt = hp[lane]; hp[lane] = f4add(tt, o); }
    else {
        float4 tt = f4add(hp[lane], o);
        ((uint2*)(h4h + (size_t)w * 128))[lane] = f4toh4(tt);
    }
}

// ---------------------------------------------------------------------------
// Final fused unpool+conv+linear: 4 threads per pixel, 4 channels each.
// P gathered as fp16 (uint2 per tap), accumulated fp32.
// ---------------------------------------------------------------------------
__global__ void k_out(const int* __restrict__ seg, const __half* __restrict__ Ph,
                      const float* __restrict__ biasf, float* __restrict__ out) {
    int gidx = blockIdx.x * blockDim.x + threadIdx.x;
    if (gidx >= NPIX * 4) return;
    int p = gidx >> 2, q = gidx & 3;
    int y = p >> 9, x = p & 511;
    float4 acc = ((const float4*)biasf)[q];
#pragma unroll
    for (int ky = 0; ky < 3; ky++) {
        int ny = y + ky - 1;
        if ((unsigned)ny >= 512u) continue;
#pragma unroll
        for (int kx = 0; kx < 3; kx++) {
            int nx = x + kx - 1;
            if ((unsigned)nx >= 512u) continue;
            int s = seg[(ny << 9) + nx];
            uint2 v = ((const uint2*)(Ph + (size_t)s * 144 + (ky * 3 + kx) * 16))[q];
            acc = f4add(acc, h4tof4(v));
        }
    }
    ((float4*)out)[gidx] = acc;
}

// ---------------------------------------------------------------------------
// Launch
// ---------------------------------------------------------------------------
extern "C" void kernel_launch(void* const* d_in, const int* in_sizes, int n_in,
                              void* d_out, int out_size) {
    const float* x   = (const float*)d_in[0];
    const int*   ei  = (const int*)  d_in[1];
    const int*   seg = (const int*)  d_in[2];
    int wi = (n_in >= 12) ? 4 : 3;
    const float* W1 = (const float*)d_in[wi + 0];
    const float* b1 = (const float*)d_in[wi + 1];
    const float* W2 = (const float*)d_in[wi + 2];
    const float* b2 = (const float*)d_in[wi + 3];
    const float* Wc = (const float*)d_in[wi + 4];
    const float* bc = (const float*)d_in[wi + 5];
    const float* Wl = (const float*)d_in[wi + 6];
    const float* bl = (const float*)d_in[wi + 7];
    float* out = (float*)d_out;
    (void)in_sizes; (void)out_size;

    Scratch* s = nullptr;
    cudaGetSymbolAddress((void**)&s, g_s);

    // --- fused prep: zero counters + transposed fp16 weights ---
    int prepN = 2 * NSP + 2 * 32768 + 144 * 128 + 16;
    k_prep<<<(prepN + 255) / 256, 256>>>(s->cnt_pix, W1, s->wp1t, W2, s->wp2t,
                                         Wc, Wl, bc, bl, s->wfoldt, s->biasf);

    // --- direct padded-CSR scatter ---
    k_scat_both<<<NPIX / 256, 256>>>(seg, s->cnt_pix, s->pix_lst,
                                     ei, s->cnt_e, s->src_lst);

    // --- mean pool pixels -> superpixels (fp16 output) ---
    k_pool<<<(NSP * 32 + 255) / 256, 256>>>(x, s->cnt_pix, s->pix_lst, s->sp);

    dim3 gAB(4, NSP / 128);
    int segGrid = (NSP * 32 + 255) / 256;
    // Layer 1: H1
    k_gemm_tc<<<gAB, 256>>>(s->sp, s->wp1t, s->abA, s->abB, NSP, 256, 1);
    k_segmax<<<segGrid, 256>>>(s->abA, s->abB, b1, s->cnt_e, s->src_lst,
                               s->hb0, s->h4, s->h4h, 0);
    // Layer 2: H2 (W2)
    k_gemm_tc<<<gAB, 256>>>(s->hb0, s->wp2t, s->abA, s->abB, NSP, 256, 1);
    k_segmax<<<segGrid, 256>>>(s->abA, s->abB, b2, s->cnt_e, s->src_lst,
                               s->hb1, s->h4, s->h4h, 1);
    // Layer 3: H3 (W2 again); h4h finalized fp16
    k_gemm_tc<<<gAB, 256>>>(s->hb1, s->wp2t, s->abA, s->abB, NSP, 256, 1);
    k_segmax<<<segGrid, 256>>>(s->abA, s->abB, b2, s->cnt_e, s->src_lst,
                               s->hb0, s->h4, s->h4h, 2);

    // --- P = H4 @ Wfold (fp16 output) ---
    dim3 gP(3, NSP / 128);
    k_gemm_tc<<<gP, 256>>>(s->h4h, s->wfoldt, nullptr, s->Ph, NSP, 144, 2);

    // --- final fused unpool + 3x3 conv + linear (fp16 P gather) ---
    k_out<<<(NPIX * 4 + 255) / 256, 256>>>(seg, s->Ph, s->biasf, out);
}